// round 2
// baseline (speedup 1.0000x reference)
#include <cuda_runtime.h>

// ---------------- problem constants ----------------
#define NPTS  50000
#define HN    32
#define INF   128
#define MIDF  64
#define OUTF  256
#define KP    15
#define KPD   (KP*MIDF)      // 960
#define KPEXT 0.48f          // 1.2 * 2.0 / 5.0
#define BNEPS 1e-6f
#define SLOPE 0.1f

// ---------------- scratch (static device globals; no allocation) ----------------
__device__ __align__(16) float g_y1 [NPTS*MIDF];   // features@w1 (pre-BN)
__device__ __align__(16) float g_wf [NPTS*KPD];    // per-point kernel-weighted features
__device__ __align__(16) float g_x2 [NPTS*MIDF];   // kpconv output (pre-BN)
__device__ __align__(16) float g_y3 [NPTS*OUTF];   // conv3 pre-BN
__device__ __align__(16) float g_ysc[NPTS*OUTF];   // shortcut pre-BN

__device__ float g_sum1[MIDF], g_sq1[MIDF], g_a1[MIDF], g_c1[MIDF];
__device__ float g_sum2[MIDF], g_sq2[MIDF], g_a2[MIDF], g_c2[MIDF];
__device__ float g_sum3[OUTF], g_sq3[OUTF], g_a3[OUTF], g_c3[OUTF];
__device__ float g_sumS[OUTF], g_sqS[OUTF], g_aS[OUTF], g_cS[OUTF];

// ---------------- zero the stat accumulators ----------------
__global__ void zero_stats_kernel() {
    int t = threadIdx.x;
    if (t < MIDF) { g_sum1[t]=0.f; g_sq1[t]=0.f; g_sum2[t]=0.f; g_sq2[t]=0.f; }
    g_sum3[t]=0.f; g_sq3[t]=0.f; g_sumS[t]=0.f; g_sqS[t]=0.f;  // t < 256
}

// ---------------- BN finalize: a = g*rsqrt(var+eps), c = b - a*mean ----------------
__global__ void finalize_kernel(const float* __restrict__ gg,
                                const float* __restrict__ bb, int which) {
    int t = threadIdx.x;
    const float* sum; const float* sq; float* a; float* c;
    switch (which) {
        case 0:  sum=g_sum1; sq=g_sq1; a=g_a1; c=g_c1; break;
        case 1:  sum=g_sum2; sq=g_sq2; a=g_a2; c=g_c2; break;
        case 2:  sum=g_sum3; sq=g_sq3; a=g_a3; c=g_c3; break;
        default: sum=g_sumS; sq=g_sqS; a=g_aS; c=g_cS; break;
    }
    const float inv = 1.0f / (float)NPTS;
    float m = sum[t] * inv;
    float v = sq[t] * inv - m * m;
    float av = gg[t] * rsqrtf(v + BNEPS);
    a[t] = av;
    c[t] = fmaf(-m, av, bb[t]);
}

// ---------------- tiled fp32 GEMM with optional input BN+LReLU transform
//                  and per-column (sum, sumsq) epilogue ----------------
// sel: 0 = feat@w1 -> g_y1 (stats1)
//      1 = g_wf@kw -> g_x2 (stats2)
//      2 = bn2lrelu(g_x2)@w3 -> g_y3 (stats3)  [TRANS]
//      3 = feat@ws -> g_ysc (statsS)
template<int BM, int BN, int BK, int TM, int TN, bool TRANS>
__global__ void gemm_kernel(const float* __restrict__ Aext,
                            const float* __restrict__ Bmat,
                            int M, int Kdim, int Ncol, int sel) {
    constexpr int THREADS = (BM/TM)*(BN/TN);
    __shared__ __align__(16) float As[BK][BM];
    __shared__ __align__(16) float Bs[BK][BN];
    __shared__ __align__(16) float redS[BN];
    __shared__ __align__(16) float redQ[BN];

    const float* A = Aext;
    float* C; float* cS; float* cQ;
    const float* tA = nullptr; const float* tC = nullptr;
    switch (sel) {
        case 0:  C=g_y1;  cS=g_sum1; cQ=g_sq1; break;
        case 1:  C=g_x2;  cS=g_sum2; cQ=g_sq2; A=g_wf; break;
        case 2:  C=g_y3;  cS=g_sum3; cQ=g_sq3; A=g_x2; tA=g_a2; tC=g_c2; break;
        default: C=g_ysc; cS=g_sumS; cQ=g_sqS; break;
    }

    int tid = threadIdx.x;
    int tx = tid % (BN/TN);
    int ty = tid / (BN/TN);
    int row0 = blockIdx.x * BM;
    int col0 = blockIdx.y * BN;

    float acc[TM][TN];
    #pragma unroll
    for (int i=0;i<TM;i++)
        #pragma unroll
        for (int j=0;j<TN;j++) acc[i][j]=0.f;

    for (int k0 = 0; k0 < Kdim; k0 += BK) {
        // A tile: BM x BK, stored transposed As[k][m]
        constexpr int A4 = (BM*BK)/(4*THREADS);
        #pragma unroll
        for (int i=0;i<A4;i++) {
            int f = tid + i*THREADS;          // float4 index within tile
            int r  = f >> 2;                  // BK/4 == 4
            int c4 = f & 3;
            int grow = row0 + r;
            float4 v = make_float4(0.f,0.f,0.f,0.f);
            if (grow < M) {
                v = *(const float4*)&A[(size_t)grow*Kdim + k0 + c4*4];
                if (TRANS) {
                    int kc = k0 + c4*4;
                    v.x = fmaf(tA[kc+0], v.x, tC[kc+0]); v.x = v.x>0.f? v.x : SLOPE*v.x;
                    v.y = fmaf(tA[kc+1], v.y, tC[kc+1]); v.y = v.y>0.f? v.y : SLOPE*v.y;
                    v.z = fmaf(tA[kc+2], v.z, tC[kc+2]); v.z = v.z>0.f? v.z : SLOPE*v.z;
                    v.w = fmaf(tA[kc+3], v.w, tC[kc+3]); v.w = v.w>0.f? v.w : SLOPE*v.w;
                }
            }
            As[c4*4+0][r] = v.x; As[c4*4+1][r] = v.y;
            As[c4*4+2][r] = v.z; As[c4*4+3][r] = v.w;
        }
        // B tile: BK x BN
        constexpr int B4 = (BK*BN)/(4*THREADS);
        #pragma unroll
        for (int i=0;i<B4;i++) {
            int f  = tid + i*THREADS;
            int kr = f / (BN/4);
            int c4 = f % (BN/4);
            *(float4*)&Bs[kr][c4*4] =
                *(const float4*)&Bmat[(size_t)(k0+kr)*Ncol + col0 + c4*4];
        }
        __syncthreads();

        #pragma unroll
        for (int kk=0; kk<BK; kk++) {
            float4 a0 = *(const float4*)&As[kk][ty*TM];
            float4 a1 = *(const float4*)&As[kk][ty*TM+4];
            float4 b0 = *(const float4*)&Bs[kk][tx*TN];
            float4 b1 = *(const float4*)&Bs[kk][tx*TN+4];
            float ra[TM] = {a0.x,a0.y,a0.z,a0.w,a1.x,a1.y,a1.z,a1.w};
            float rb[TN] = {b0.x,b0.y,b0.z,b0.w,b1.x,b1.y,b1.z,b1.w};
            #pragma unroll
            for (int i=0;i<TM;i++)
                #pragma unroll
                for (int j=0;j<TN;j++)
                    acc[i][j] = fmaf(ra[i], rb[j], acc[i][j]);
        }
        __syncthreads();
    }

    // store C
    #pragma unroll
    for (int i=0;i<TM;i++) {
        int grow = row0 + ty*TM + i;
        if (grow < M) {
            #pragma unroll
            for (int j=0;j<TN;j+=4) {
                float4 v = make_float4(acc[i][j],acc[i][j+1],acc[i][j+2],acc[i][j+3]);
                *(float4*)&C[(size_t)grow*Ncol + col0 + tx*TN + j] = v;
            }
        }
    }

    // per-column sum / sumsq (only valid rows)
    for (int j = tid; j < BN; j += THREADS) { redS[j]=0.f; redQ[j]=0.f; }
    __syncthreads();
    #pragma unroll
    for (int j=0;j<TN;j++) {
        float s=0.f, q=0.f;
        #pragma unroll
        for (int i=0;i<TM;i++) {
            int grow = row0 + ty*TM + i;
            if (grow < M) { float v = acc[i][j]; s += v; q += v*v; }
        }
        atomicAdd(&redS[tx*TN+j], s);
        atomicAdd(&redQ[tx*TN+j], q);
    }
    __syncthreads();
    for (int j = tid; j < BN; j += THREADS) {
        atomicAdd(&cS[col0+j], redS[j]);
        atomicAdd(&cQ[col0+j], redQ[j]);
    }
}

// ---------------- KPConv gather: per point compute infl[h][k] and
//                  wf[k][d] = sum_h infl[h][k]*nf[h][d], write to g_wf ----------------
// block = 256 threads = 4 points, 64 threads per point (thread t owns feature d=t)
__global__ void kpconv_kernel(const float* __restrict__ qpts,
                              const float* __restrict__ spts,
                              const int*   __restrict__ inds,
                              const float* __restrict__ kpts) {
    __shared__ __align__(16) float s_infl[4][HN][16];
    __shared__ __align__(16) float s_nf[4][HN][MIDF];
    __shared__ int   s_idx[4][HN];
    __shared__ float s_del[4][HN][3];
    __shared__ float s_kp[KP*3];

    int tid = threadIdx.x;
    int g = tid >> 6;
    int t = tid & 63;
    int n = blockIdx.x*4 + g;

    if (tid < KP*3) s_kp[tid] = kpts[tid];
    if (t < HN) {
        int idx = inds[n*HN + t];
        s_idx[g][t] = idx;
        float qx = qpts[n*3+0], qy = qpts[n*3+1], qz = qpts[n*3+2];
        s_del[g][t][0] = spts[idx*3+0] - qx;
        s_del[g][t][1] = spts[idx*3+1] - qy;
        s_del[g][t][2] = spts[idx*3+2] - qz;
        s_infl[g][t][15] = 0.f;  // pad lane
    }
    __syncthreads();

    // influence: 32*15 values per point, 64 threads
    for (int i = t; i < HN*KP; i += 64) {
        int h = i / KP;
        int k = i - h*KP;
        float dx = s_del[g][h][0] - s_kp[k*3+0];
        float dy = s_del[g][h][1] - s_kp[k*3+1];
        float dz = s_del[g][h][2] - s_kp[k*3+2];
        float sq = dx*dx + dy*dy + dz*dz;
        float dist = sqrtf(fmaxf(sq, 1e-12f));
        s_infl[g][h][k] = fmaxf(0.f, 1.f - dist*(1.f/KPEXT));
    }

    // gather neighbor features through bn1 + lrelu (y1 table is L2-resident)
    float av = g_a1[t], cv = g_c1[t];
    #pragma unroll 4
    for (int h = 0; h < HN; h++) {
        float v = g_y1[(size_t)s_idx[g][h]*MIDF + t];
        v = fmaf(av, v, cv);
        v = v > 0.f ? v : SLOPE*v;
        s_nf[g][h][t] = v;
    }
    __syncthreads();

    // wf[k][t] = sum_h infl[h][k]*nf[h][t]
    float acc[KP];
    #pragma unroll
    for (int k=0;k<KP;k++) acc[k]=0.f;
    #pragma unroll 4
    for (int h=0; h<HN; h++) {
        float r = s_nf[g][h][t];
        float4 f0 = *(const float4*)&s_infl[g][h][0];
        float4 f1 = *(const float4*)&s_infl[g][h][4];
        float4 f2 = *(const float4*)&s_infl[g][h][8];
        float4 f3 = *(const float4*)&s_infl[g][h][12];
        acc[0]  = fmaf(f0.x, r, acc[0]);  acc[1]  = fmaf(f0.y, r, acc[1]);
        acc[2]  = fmaf(f0.z, r, acc[2]);  acc[3]  = fmaf(f0.w, r, acc[3]);
        acc[4]  = fmaf(f1.x, r, acc[4]);  acc[5]  = fmaf(f1.y, r, acc[5]);
        acc[6]  = fmaf(f1.z, r, acc[6]);  acc[7]  = fmaf(f1.w, r, acc[7]);
        acc[8]  = fmaf(f2.x, r, acc[8]);  acc[9]  = fmaf(f2.y, r, acc[9]);
        acc[10] = fmaf(f2.z, r, acc[10]); acc[11] = fmaf(f2.w, r, acc[11]);
        acc[12] = fmaf(f3.x, r, acc[12]); acc[13] = fmaf(f3.y, r, acc[13]);
        acc[14] = fmaf(f3.z, r, acc[14]);
    }
    size_t base = (size_t)n*KPD + t;
    #pragma unroll
    for (int k=0;k<KP;k++) g_wf[base + (size_t)k*MIDF] = acc[k];
}

// ---------------- final: out = lrelu( lrelu(bn3(y3)) + lrelu(bnS(ysc)) ) ----------------
__global__ void final_kernel(float* __restrict__ out) {
    int i = blockIdx.x*blockDim.x + threadIdx.x;     // float4 index
    const int total4 = NPTS*OUTF/4;
    if (i >= total4) return;
    int c0 = (i << 2) & (OUTF-1);
    float4 y = *(const float4*)&g_y3[(size_t)i*4];
    float4 s = *(const float4*)&g_ysc[(size_t)i*4];
    float4 o;
    {
        float vy[4] = {y.x,y.y,y.z,y.w};
        float vs[4] = {s.x,s.y,s.z,s.w};
        float vo[4];
        #pragma unroll
        for (int j=0;j<4;j++) {
            int c = c0 + j;
            float a = fmaf(g_a3[c], vy[j], g_c3[c]); a = a>0.f? a : SLOPE*a;
            float b = fmaf(g_aS[c], vs[j], g_cS[c]); b = b>0.f? b : SLOPE*b;
            float r = a + b;
            vo[j] = r>0.f? r : SLOPE*r;
        }
        o = make_float4(vo[0],vo[1],vo[2],vo[3]);
    }
    *(float4*)&out[(size_t)i*4] = o;
}

// ---------------- launcher ----------------
extern "C" void kernel_launch(void* const* d_in, const int* in_sizes, int n_in,
                              void* d_out, int out_size) {
    const float* q    = (const float*)d_in[0];
    const float* s    = (const float*)d_in[1];
    const int*   inds = (const int*)  d_in[2];
    const float* feat = (const float*)d_in[3];
    const float* kp   = (const float*)d_in[4];
    const float* w1   = (const float*)d_in[5];
    const float* g1   = (const float*)d_in[6];
    const float* b1   = (const float*)d_in[7];
    const float* kw   = (const float*)d_in[8];
    const float* g2   = (const float*)d_in[9];
    const float* b2   = (const float*)d_in[10];
    const float* w3   = (const float*)d_in[11];
    const float* g3   = (const float*)d_in[12];
    const float* b3   = (const float*)d_in[13];
    const float* ws   = (const float*)d_in[14];
    const float* gs   = (const float*)d_in[15];
    const float* bs   = (const float*)d_in[16];
    float* out = (float*)d_out;

    const int MT = (NPTS + 127) / 128;   // 391 row tiles

    zero_stats_kernel<<<1, 256>>>();

    // conv1: y1 = feat @ w1, stats1
    gemm_kernel<128,64,16,8,8,false><<<dim3(MT,1), 128>>>(feat, w1, NPTS, INF, MIDF, 0);
    finalize_kernel<<<1, MIDF>>>(g1, b1, 0);

    // KPConv gather -> wf
    kpconv_kernel<<<NPTS/4, 256>>>(q, s, inds, kp);

    // x2 = wf @ kw  (kw viewed as [960,64]), stats2
    gemm_kernel<128,64,16,8,8,false><<<dim3(MT,1), 128>>>(nullptr, kw, NPTS, KPD, MIDF, 1);
    finalize_kernel<<<1, MIDF>>>(g2, b2, 1);

    // conv3: y3 = lrelu(bn2(x2)) @ w3, stats3
    gemm_kernel<128,128,16,8,8,true ><<<dim3(MT,2), 256>>>(nullptr, w3, NPTS, MIDF, OUTF, 2);
    // shortcut: ysc = feat @ ws, statsS
    gemm_kernel<128,128,16,8,8,false><<<dim3(MT,2), 256>>>(feat, ws, NPTS, INF, OUTF, 3);

    finalize_kernel<<<1, OUTF>>>(g3, b3, 2);
    finalize_kernel<<<1, OUTF>>>(gs, bs, 3);

    final_kernel<<<(NPTS*OUTF/4 + 255)/256, 256>>>(out);
}

// round 3
// speedup vs baseline: 1.1320x; 1.1320x over previous
#include <cuda_runtime.h>

// ---------------- problem constants ----------------
#define NPTS  50000
#define HN    32
#define INF   128
#define MIDF  64
#define OUTF  256
#define KP    15
#define KPD   (KP*MIDF)      // 960
#define KPEXT 0.48f          // 1.2 * 2.0 / 5.0
#define BNEPS 1e-6f
#define SLOPE 0.1f

// ---------------- scratch (static device globals; no allocation) ----------------
__device__ __align__(16) float g_y1 [NPTS*MIDF];   // features@w1 (pre-BN)
__device__ __align__(16) float g_wf [NPTS*KPD];    // per-point kernel-weighted features
__device__ __align__(16) float g_x2 [NPTS*MIDF];   // kpconv output (pre-BN)
__device__ __align__(16) float g_y3 [NPTS*OUTF];   // conv3 pre-BN
__device__ __align__(16) float g_ysc[NPTS*OUTF];   // shortcut pre-BN

__device__ __align__(16) float g_sum1[MIDF], g_sq1[MIDF], g_a1[MIDF], g_c1[MIDF];
__device__ __align__(16) float g_sum2[MIDF], g_sq2[MIDF], g_a2[MIDF], g_c2[MIDF];
__device__ __align__(16) float g_sum3[OUTF], g_sq3[OUTF], g_a3[OUTF], g_c3[OUTF];
__device__ __align__(16) float g_sumS[OUTF], g_sqS[OUTF], g_aS[OUTF], g_cS[OUTF];

// ---------------- zero the stat accumulators ----------------
__global__ void zero_stats_kernel() {
    int t = threadIdx.x;
    if (t < MIDF) { g_sum1[t]=0.f; g_sq1[t]=0.f; g_sum2[t]=0.f; g_sq2[t]=0.f; }
    g_sum3[t]=0.f; g_sq3[t]=0.f; g_sumS[t]=0.f; g_sqS[t]=0.f;  // t < 256
}

// ---------------- BN finalize: a = g*rsqrt(var+eps), c = b - a*mean ----------------
__global__ void finalize_kernel(const float* __restrict__ gg,
                                const float* __restrict__ bb, int which) {
    int t = threadIdx.x;
    const float* sum; const float* sq; float* a; float* c;
    switch (which) {
        case 0:  sum=g_sum1; sq=g_sq1; a=g_a1; c=g_c1; break;
        case 1:  sum=g_sum2; sq=g_sq2; a=g_a2; c=g_c2; break;
        case 2:  sum=g_sum3; sq=g_sq3; a=g_a3; c=g_c3; break;
        default: sum=g_sumS; sq=g_sqS; a=g_aS; c=g_cS; break;
    }
    const float inv = 1.0f / (float)NPTS;
    float m = sum[t] * inv;
    float v = sq[t] * inv - m * m;
    float av = gg[t] * rsqrtf(v + BNEPS);
    a[t] = av;
    c[t] = fmaf(-m, av, bb[t]);
}

// ---------------- tiled fp32 GEMM with optional input BN+LReLU transform
//                  and per-column (sum, sumsq) epilogue ----------------
template<int BM, int BN, int BK, int TM, int TN, bool TRANS>
__global__ void gemm_kernel(const float* __restrict__ Aext,
                            const float* __restrict__ Bmat,
                            int M, int Kdim, int Ncol, int sel) {
    constexpr int THREADS = (BM/TM)*(BN/TN);
    __shared__ __align__(16) float As[BK][BM];
    __shared__ __align__(16) float Bs[BK][BN];
    __shared__ __align__(16) float redS[BN];
    __shared__ __align__(16) float redQ[BN];

    const float* A = Aext;
    float* C; float* cS; float* cQ;
    const float* tA = nullptr; const float* tC = nullptr;
    switch (sel) {
        case 0:  C=g_y1;  cS=g_sum1; cQ=g_sq1; break;
        case 1:  C=g_x2;  cS=g_sum2; cQ=g_sq2; A=g_wf; break;
        case 2:  C=g_y3;  cS=g_sum3; cQ=g_sq3; A=g_x2; tA=g_a2; tC=g_c2; break;
        default: C=g_ysc; cS=g_sumS; cQ=g_sqS; break;
    }

    int tid = threadIdx.x;
    int tx = tid % (BN/TN);
    int ty = tid / (BN/TN);
    int row0 = blockIdx.x * BM;
    int col0 = blockIdx.y * BN;

    float acc[TM][TN];
    #pragma unroll
    for (int i=0;i<TM;i++)
        #pragma unroll
        for (int j=0;j<TN;j++) acc[i][j]=0.f;

    for (int k0 = 0; k0 < Kdim; k0 += BK) {
        // A tile: BM x BK, stored transposed As[k][m]
        constexpr int A4 = (BM*BK)/(4*THREADS);
        #pragma unroll
        for (int i=0;i<A4;i++) {
            int f = tid + i*THREADS;          // float4 index within tile
            int r  = f >> 2;                  // BK/4 == 4
            int c4 = f & 3;
            int grow = row0 + r;
            float4 v = make_float4(0.f,0.f,0.f,0.f);
            if (grow < M) {
                v = *(const float4*)&A[(size_t)grow*Kdim + k0 + c4*4];
                if (TRANS) {
                    int kc = k0 + c4*4;
                    v.x = fmaf(tA[kc+0], v.x, tC[kc+0]); v.x = v.x>0.f? v.x : SLOPE*v.x;
                    v.y = fmaf(tA[kc+1], v.y, tC[kc+1]); v.y = v.y>0.f? v.y : SLOPE*v.y;
                    v.z = fmaf(tA[kc+2], v.z, tC[kc+2]); v.z = v.z>0.f? v.z : SLOPE*v.z;
                    v.w = fmaf(tA[kc+3], v.w, tC[kc+3]); v.w = v.w>0.f? v.w : SLOPE*v.w;
                }
            }
            As[c4*4+0][r] = v.x; As[c4*4+1][r] = v.y;
            As[c4*4+2][r] = v.z; As[c4*4+3][r] = v.w;
        }
        // B tile: BK x BN
        constexpr int B4 = (BK*BN)/(4*THREADS);
        #pragma unroll
        for (int i=0;i<B4;i++) {
            int f  = tid + i*THREADS;
            int kr = f / (BN/4);
            int c4 = f % (BN/4);
            *(float4*)&Bs[kr][c4*4] =
                *(const float4*)&Bmat[(size_t)(k0+kr)*Ncol + col0 + c4*4];
        }
        __syncthreads();

        #pragma unroll
        for (int kk=0; kk<BK; kk++) {
            float4 a0 = *(const float4*)&As[kk][ty*TM];
            float4 a1 = *(const float4*)&As[kk][ty*TM+4];
            float4 b0 = *(const float4*)&Bs[kk][tx*TN];
            float4 b1 = *(const float4*)&Bs[kk][tx*TN+4];
            float ra[TM] = {a0.x,a0.y,a0.z,a0.w,a1.x,a1.y,a1.z,a1.w};
            float rb[TN] = {b0.x,b0.y,b0.z,b0.w,b1.x,b1.y,b1.z,b1.w};
            #pragma unroll
            for (int i=0;i<TM;i++)
                #pragma unroll
                for (int j=0;j<TN;j++)
                    acc[i][j] = fmaf(ra[i], rb[j], acc[i][j]);
        }
        __syncthreads();
    }

    // store C
    #pragma unroll
    for (int i=0;i<TM;i++) {
        int grow = row0 + ty*TM + i;
        if (grow < M) {
            #pragma unroll
            for (int j=0;j<TN;j+=4) {
                float4 v = make_float4(acc[i][j],acc[i][j+1],acc[i][j+2],acc[i][j+3]);
                *(float4*)&C[(size_t)grow*Ncol + col0 + tx*TN + j] = v;
            }
        }
    }

    // per-column sum / sumsq (only valid rows)
    for (int j = tid; j < BN; j += THREADS) { redS[j]=0.f; redQ[j]=0.f; }
    __syncthreads();
    #pragma unroll
    for (int j=0;j<TN;j++) {
        float s=0.f, q=0.f;
        #pragma unroll
        for (int i=0;i<TM;i++) {
            int grow = row0 + ty*TM + i;
            if (grow < M) { float v = acc[i][j]; s += v; q += v*v; }
        }
        atomicAdd(&redS[tx*TN+j], s);
        atomicAdd(&redQ[tx*TN+j], q);
    }
    __syncthreads();
    for (int j = tid; j < BN; j += THREADS) {
        atomicAdd(&cS[col0+j], redS[j]);
        atomicAdd(&cQ[col0+j], redQ[j]);
    }
}

// ---------------- KPConv gather, v2: high FMA density ----------------
// Block = 256 threads = 16 points, 16 threads/point, 4 channels/thread.
// Per (h, thread): 1 LDG.128 (nf direct from L2) + 4 LDS.128 (infl bcast) + 60 FMA.
#define PPB 16                    // points per block
#define IPP 516                   // padded infl floats per point (512 + 4 pad)
__global__ void __launch_bounds__(256) kpconv_kernel(
                              const float* __restrict__ qpts,
                              const float* __restrict__ spts,
                              const int*   __restrict__ inds,
                              const float* __restrict__ kpts) {
    __shared__ __align__(16) float s_infl[PPB*IPP];     // [p][h*16 + k]
    __shared__ __align__(16) float s_del[PPB][HN][3];
    __shared__ int   s_idx[PPB][HN];
    __shared__ float s_kp[KP*3];

    const int tid = threadIdx.x;
    const int g = tid >> 4;          // point within block
    const int t = tid & 15;          // channel group (owns channels 4t..4t+3)
    const int n0 = blockIdx.x * PPB;
    const int n = n0 + g;

    if (tid < KP*3) s_kp[tid] = kpts[tid];

    // ---- phase 1: load indices + deltas (512 neighbors, 2 per thread) ----
    #pragma unroll
    for (int i = tid; i < PPB*HN; i += 256) {
        int p = i >> 5;              // point
        int h = i & 31;              // neighbor
        int np = n0 + p;
        int idx = inds[np*HN + h];
        s_idx[p][h] = idx;
        s_del[p][h][0] = spts[idx*3+0] - qpts[np*3+0];
        s_del[p][h][1] = spts[idx*3+1] - qpts[np*3+1];
        s_del[p][h][2] = spts[idx*3+2] - qpts[np*3+2];
    }
    __syncthreads();

    // ---- phase 2: influence. thread t handles k=t (t==15 -> pad 0), j = h ----
    {
        float kx = 0.f, ky = 0.f, kz = 0.f;
        if (t < KP) { kx = s_kp[t*3+0]; ky = s_kp[t*3+1]; kz = s_kp[t*3+2]; }
        float* inflp = &s_infl[g*IPP];
        #pragma unroll 4
        for (int j = 0; j < HN; j++) {
            float val = 0.f;
            if (t < KP) {
                float dx = s_del[g][j][0] - kx;
                float dy = s_del[g][j][1] - ky;
                float dz = s_del[g][j][2] - kz;
                float sq = fmaf(dx,dx,fmaf(dy,dy,dz*dz));
                float dist = sqrtf(fmaxf(sq, 1e-12f));
                val = fmaxf(0.f, 1.f - dist*(1.f/KPEXT));
            }
            inflp[j*16 + t] = val;
        }
    }
    __syncthreads();

    // ---- phase 3: wf[k][4t..4t+3] = sum_h infl[h][k] * bn1lrelu(y1[idx[h]][4t..]) ----
    const float4 a1 = *(const float4*)&g_a1[4*t];
    const float4 c1 = *(const float4*)&g_c1[4*t];
    float acc[KP][4];
    #pragma unroll
    for (int k=0;k<KP;k++) { acc[k][0]=0.f; acc[k][1]=0.f; acc[k][2]=0.f; acc[k][3]=0.f; }

    const float* inflp = &s_infl[g*IPP];
    #pragma unroll 2
    for (int h = 0; h < HN; h++) {
        int idx = s_idx[g][h];
        float4 v = *(const float4*)&g_y1[(size_t)idx*MIDF + 4*t];
        v.x = fmaf(a1.x, v.x, c1.x); v.x = v.x>0.f ? v.x : SLOPE*v.x;
        v.y = fmaf(a1.y, v.y, c1.y); v.y = v.y>0.f ? v.y : SLOPE*v.y;
        v.z = fmaf(a1.z, v.z, c1.z); v.z = v.z>0.f ? v.z : SLOPE*v.z;
        v.w = fmaf(a1.w, v.w, c1.w); v.w = v.w>0.f ? v.w : SLOPE*v.w;

        float4 f0 = *(const float4*)&inflp[h*16 + 0];
        float4 f1 = *(const float4*)&inflp[h*16 + 4];
        float4 f2 = *(const float4*)&inflp[h*16 + 8];
        float4 f3 = *(const float4*)&inflp[h*16 + 12];
        const float fk[16] = {f0.x,f0.y,f0.z,f0.w, f1.x,f1.y,f1.z,f1.w,
                              f2.x,f2.y,f2.z,f2.w, f3.x,f3.y,f3.z,f3.w};
        #pragma unroll
        for (int k=0;k<KP;k++) {
            acc[k][0] = fmaf(fk[k], v.x, acc[k][0]);
            acc[k][1] = fmaf(fk[k], v.y, acc[k][1]);
            acc[k][2] = fmaf(fk[k], v.z, acc[k][2]);
            acc[k][3] = fmaf(fk[k], v.w, acc[k][3]);
        }
    }

    // ---- store: STG.128, coalesced 256B per (point, k) ----
    size_t base = (size_t)n*KPD + 4*t;
    #pragma unroll
    for (int k=0;k<KP;k++) {
        *(float4*)&g_wf[base + (size_t)k*MIDF] =
            make_float4(acc[k][0], acc[k][1], acc[k][2], acc[k][3]);
    }
}

// ---------------- final: out = lrelu( lrelu(bn3(y3)) + lrelu(bnS(ysc)) ) ----------------
__global__ void final_kernel(float* __restrict__ out) {
    int i = blockIdx.x*blockDim.x + threadIdx.x;     // float4 index
    const int total4 = NPTS*OUTF/4;
    if (i >= total4) return;
    int c0 = (i << 2) & (OUTF-1);
    float4 y = *(const float4*)&g_y3[(size_t)i*4];
    float4 s = *(const float4*)&g_ysc[(size_t)i*4];
    float4 o;
    {
        float vy[4] = {y.x,y.y,y.z,y.w};
        float vs[4] = {s.x,s.y,s.z,s.w};
        float vo[4];
        #pragma unroll
        for (int j=0;j<4;j++) {
            int c = c0 + j;
            float a = fmaf(g_a3[c], vy[j], g_c3[c]); a = a>0.f? a : SLOPE*a;
            float b = fmaf(g_aS[c], vs[j], g_cS[c]); b = b>0.f? b : SLOPE*b;
            float r = a + b;
            vo[j] = r>0.f? r : SLOPE*r;
        }
        o = make_float4(vo[0],vo[1],vo[2],vo[3]);
    }
    *(float4*)&out[(size_t)i*4] = o;
}

// ---------------- launcher ----------------
extern "C" void kernel_launch(void* const* d_in, const int* in_sizes, int n_in,
                              void* d_out, int out_size) {
    const float* q    = (const float*)d_in[0];
    const float* s    = (const float*)d_in[1];
    const int*   inds = (const int*)  d_in[2];
    const float* feat = (const float*)d_in[3];
    const float* kp   = (const float*)d_in[4];
    const float* w1   = (const float*)d_in[5];
    const float* g1   = (const float*)d_in[6];
    const float* b1   = (const float*)d_in[7];
    const float* kw   = (const float*)d_in[8];
    const float* g2   = (const float*)d_in[9];
    const float* b2   = (const float*)d_in[10];
    const float* w3   = (const float*)d_in[11];
    const float* g3   = (const float*)d_in[12];
    const float* b3   = (const float*)d_in[13];
    const float* ws   = (const float*)d_in[14];
    const float* gs   = (const float*)d_in[15];
    const float* bs   = (const float*)d_in[16];
    float* out = (float*)d_out;

    const int MT = (NPTS + 127) / 128;   // 391 row tiles

    zero_stats_kernel<<<1, 256>>>();

    // conv1: y1 = feat @ w1, stats1
    gemm_kernel<128,64,16,8,8,false><<<dim3(MT,1), 128>>>(feat, w1, NPTS, INF, MIDF, 0);
    finalize_kernel<<<1, MIDF>>>(g1, b1, 0);

    // KPConv gather -> wf
    kpconv_kernel<<<NPTS/PPB, 256>>>(q, s, inds, kp);

    // x2 = wf @ kw  (kw viewed as [960,64]), stats2
    gemm_kernel<128,64,16,8,8,false><<<dim3(MT,1), 128>>>(nullptr, kw, NPTS, KPD, MIDF, 1);
    finalize_kernel<<<1, MIDF>>>(g2, b2, 1);

    // conv3: y3 = lrelu(bn2(x2)) @ w3, stats3
    gemm_kernel<128,128,16,8,8,true ><<<dim3(MT,2), 256>>>(nullptr, w3, NPTS, MIDF, OUTF, 2);
    // shortcut: ysc = feat @ ws, statsS
    gemm_kernel<128,128,16,8,8,false><<<dim3(MT,2), 256>>>(feat, ws, NPTS, INF, OUTF, 3);

    finalize_kernel<<<1, OUTF>>>(g3, b3, 2);
    finalize_kernel<<<1, OUTF>>>(gs, bs, 3);

    final_kernel<<<(NPTS*OUTF/4 + 255)/256, 256>>>(out);
}

// round 4
// speedup vs baseline: 1.2240x; 1.0813x over previous
#include <cuda_runtime.h>

// ---------------- problem constants ----------------
#define NPTS  50000
#define HN    32
#define INF   128
#define MIDF  64
#define OUTF  256
#define KP    15
#define KPD   (KP*MIDF)      // 960
#define KPEXT 0.48f          // 1.2 * 2.0 / 5.0
#define BNEPS 1e-6f
#define SLOPE 0.1f

typedef unsigned long long ull;

// ---------------- packed f32x2 helpers (Blackwell FFMA2 path) ----------------
__device__ __forceinline__ ull pack2(float x, float y) {
    ull r; asm("mov.b64 %0, {%1, %2};" : "=l"(r) : "f"(x), "f"(y)); return r;
}
__device__ __forceinline__ void unpack2(ull v, float& x, float& y) {
    asm("mov.b64 {%0, %1}, %2;" : "=f"(x), "=f"(y) : "l"(v));
}
__device__ __forceinline__ void ffma2(ull& d, ull a, ull b) {
    asm("fma.rn.f32x2 %0, %1, %2, %0;" : "+l"(d) : "l"(a), "l"(b));
}

// ---------------- scratch (static device globals; no allocation) ----------------
__device__ __align__(16) float g_y1 [NPTS*MIDF];   // features@w1 (pre-BN)
__device__ __align__(16) float g_wf [NPTS*KPD];    // per-point kernel-weighted features
__device__ __align__(16) float g_x2 [NPTS*MIDF];   // kpconv output (pre-BN)
__device__ __align__(16) float g_y3 [NPTS*OUTF];   // conv3 pre-BN
__device__ __align__(16) float g_ysc[NPTS*OUTF];   // shortcut pre-BN

__device__ __align__(16) float g_sum1[MIDF], g_sq1[MIDF], g_a1[MIDF], g_c1[MIDF];
__device__ __align__(16) float g_sum2[MIDF], g_sq2[MIDF], g_a2[MIDF], g_c2[MIDF];
__device__ __align__(16) float g_sum3[OUTF], g_sq3[OUTF], g_a3[OUTF], g_c3[OUTF];
__device__ __align__(16) float g_sumS[OUTF], g_sqS[OUTF], g_aS[OUTF], g_cS[OUTF];

// ---------------- zero the stat accumulators ----------------
__global__ void zero_stats_kernel() {
    int t = threadIdx.x;
    if (t < MIDF) { g_sum1[t]=0.f; g_sq1[t]=0.f; g_sum2[t]=0.f; g_sq2[t]=0.f; }
    g_sum3[t]=0.f; g_sq3[t]=0.f; g_sumS[t]=0.f; g_sqS[t]=0.f;  // t < 256
}

// ---------------- BN finalize: a = g*rsqrt(var+eps), c = b - a*mean ----------------
__global__ void finalize_kernel(const float* __restrict__ gg,
                                const float* __restrict__ bb, int which) {
    int t = threadIdx.x;
    const float* sum; const float* sq; float* a; float* c;
    switch (which) {
        case 0:  sum=g_sum1; sq=g_sq1; a=g_a1; c=g_c1; break;
        case 1:  sum=g_sum2; sq=g_sq2; a=g_a2; c=g_c2; break;
        case 2:  sum=g_sum3; sq=g_sq3; a=g_a3; c=g_c3; break;
        default: sum=g_sumS; sq=g_sqS; a=g_aS; c=g_cS; break;
    }
    const float inv = 1.0f / (float)NPTS;
    float m = sum[t] * inv;
    float v = sq[t] * inv - m * m;
    float av = gg[t] * rsqrtf(v + BNEPS);
    a[t] = av;
    c[t] = fmaf(-m, av, bb[t]);
}

// ---------------- tiled fp32 GEMM, FFMA2 (f32x2) inner loop,
//                  optional input BN+LReLU transform, stats epilogue ----------------
template<int BM, int BN, int BK, int TM, int TN, bool TRANS>
__global__ void gemm_kernel(const float* __restrict__ Aext,
                            const float* __restrict__ Bmat,
                            int M, int Kdim, int Ncol, int sel) {
    constexpr int THREADS = (BM/TM)*(BN/TN);
    __shared__ __align__(16) float As[BK][BM];
    __shared__ __align__(16) float Bs[BK][BN];
    __shared__ __align__(16) float redS[BN];
    __shared__ __align__(16) float redQ[BN];

    const float* A = Aext;
    float* C; float* cS; float* cQ;
    const float* tA = nullptr; const float* tC = nullptr;
    switch (sel) {
        case 0:  C=g_y1;  cS=g_sum1; cQ=g_sq1; break;
        case 1:  C=g_x2;  cS=g_sum2; cQ=g_sq2; A=g_wf; break;
        case 2:  C=g_y3;  cS=g_sum3; cQ=g_sq3; A=g_x2; tA=g_a2; tC=g_c2; break;
        default: C=g_ysc; cS=g_sumS; cQ=g_sqS; break;
    }

    int tid = threadIdx.x;
    int tx = tid % (BN/TN);
    int ty = tid / (BN/TN);
    int row0 = blockIdx.x * BM;
    int col0 = blockIdx.y * BN;

    ull acc2[TM][TN/2];
    #pragma unroll
    for (int i=0;i<TM;i++)
        #pragma unroll
        for (int j=0;j<TN/2;j++) acc2[i][j]=0ull;

    for (int k0 = 0; k0 < Kdim; k0 += BK) {
        // A tile: BM x BK, stored transposed As[k][m]
        constexpr int A4 = (BM*BK)/(4*THREADS);
        #pragma unroll
        for (int i=0;i<A4;i++) {
            int f = tid + i*THREADS;          // float4 index within tile
            int r  = f >> 2;                  // BK/4 == 4
            int c4 = f & 3;
            int grow = row0 + r;
            float4 v = make_float4(0.f,0.f,0.f,0.f);
            if (grow < M) {
                v = *(const float4*)&A[(size_t)grow*Kdim + k0 + c4*4];
                if (TRANS) {
                    int kc = k0 + c4*4;
                    v.x = fmaf(tA[kc+0], v.x, tC[kc+0]); v.x = fmaxf(v.x, SLOPE*v.x);
                    v.y = fmaf(tA[kc+1], v.y, tC[kc+1]); v.y = fmaxf(v.y, SLOPE*v.y);
                    v.z = fmaf(tA[kc+2], v.z, tC[kc+2]); v.z = fmaxf(v.z, SLOPE*v.z);
                    v.w = fmaf(tA[kc+3], v.w, tC[kc+3]); v.w = fmaxf(v.w, SLOPE*v.w);
                }
            }
            As[c4*4+0][r] = v.x; As[c4*4+1][r] = v.y;
            As[c4*4+2][r] = v.z; As[c4*4+3][r] = v.w;
        }
        // B tile: BK x BN
        constexpr int B4 = (BK*BN)/(4*THREADS);
        #pragma unroll
        for (int i=0;i<B4;i++) {
            int f  = tid + i*THREADS;
            int kr = f / (BN/4);
            int c4 = f % (BN/4);
            *(float4*)&Bs[kr][c4*4] =
                *(const float4*)&Bmat[(size_t)(k0+kr)*Ncol + col0 + c4*4];
        }
        __syncthreads();

        #pragma unroll
        for (int kk=0; kk<BK; kk++) {
            float4 a0 = *(const float4*)&As[kk][ty*TM];
            float4 a1 = *(const float4*)&As[kk][ty*TM+4];
            ulonglong2 bb0 = *(const ulonglong2*)&Bs[kk][tx*TN];
            ulonglong2 bb1 = *(const ulonglong2*)&Bs[kk][tx*TN+4];
            ull rb2[4] = {bb0.x, bb0.y, bb1.x, bb1.y};
            float ra[TM] = {a0.x,a0.y,a0.z,a0.w,a1.x,a1.y,a1.z,a1.w};
            #pragma unroll
            for (int i=0;i<TM;i++) {
                ull ra2 = pack2(ra[i], ra[i]);
                #pragma unroll
                for (int j=0;j<TN/2;j++)
                    ffma2(acc2[i][j], ra2, rb2[j]);
            }
        }
        __syncthreads();
    }

    // unpack accumulators
    float acc[TM][TN];
    #pragma unroll
    for (int i=0;i<TM;i++)
        #pragma unroll
        for (int j=0;j<TN/2;j++)
            unpack2(acc2[i][j], acc[i][2*j], acc[i][2*j+1]);

    // store C
    #pragma unroll
    for (int i=0;i<TM;i++) {
        int grow = row0 + ty*TM + i;
        if (grow < M) {
            #pragma unroll
            for (int j=0;j<TN;j+=4) {
                float4 v = make_float4(acc[i][j],acc[i][j+1],acc[i][j+2],acc[i][j+3]);
                *(float4*)&C[(size_t)grow*Ncol + col0 + tx*TN + j] = v;
            }
        }
    }

    // per-column sum / sumsq (only valid rows)
    for (int j = tid; j < BN; j += THREADS) { redS[j]=0.f; redQ[j]=0.f; }
    __syncthreads();
    #pragma unroll
    for (int j=0;j<TN;j++) {
        float s=0.f, q=0.f;
        #pragma unroll
        for (int i=0;i<TM;i++) {
            int grow = row0 + ty*TM + i;
            if (grow < M) { float v = acc[i][j]; s += v; q += v*v; }
        }
        atomicAdd(&redS[tx*TN+j], s);
        atomicAdd(&redQ[tx*TN+j], q);
    }
    __syncthreads();
    for (int j = tid; j < BN; j += THREADS) {
        atomicAdd(&cS[col0+j], redS[j]);
        atomicAdd(&cQ[col0+j], redQ[j]);
    }
}

// ---------------- KPConv gather, v3: warp == point, 2 channels/thread ----------------
// 256 threads = 8 warps = 8 points. Lane owns channels (2*lane, 2*lane+1).
// Per h per warp: 4x LDS.128 (broadcast, conflict-free) + 1 LDG.64 + 16 FFMA2.
#define PPB 8                     // points per block (= warps)
__global__ void __launch_bounds__(256) kpconv_kernel(
                              const float* __restrict__ qpts,
                              const float* __restrict__ spts,
                              const int*   __restrict__ inds,
                              const float* __restrict__ kpts) {
    __shared__ __align__(16) float s_infl[PPB][HN*16];  // [p][h*16+k], k=15 is pad=0
    __shared__ __align__(16) float s_del[PPB][HN][3];
    __shared__ int   s_idx[PPB][HN];
    __shared__ float s_kp[KP*3];

    const int tid  = threadIdx.x;
    const int w    = tid >> 5;        // point within block
    const int lane = tid & 31;
    const int n = blockIdx.x * PPB + w;

    if (tid < KP*3) s_kp[tid] = kpts[tid];

    // ---- phase 1: lane = neighbor h ----
    {
        int idx = inds[n*HN + lane];
        s_idx[w][lane] = idx;
        s_del[w][lane][0] = spts[idx*3+0] - qpts[n*3+0];
        s_del[w][lane][1] = spts[idx*3+1] - qpts[n*3+1];
        s_del[w][lane][2] = spts[idx*3+2] - qpts[n*3+2];
    }
    __syncthreads();   // covers s_kp + s_del/s_idx

    // ---- phase 2: lane -> (k = lane&15, h-half = lane>>4); conflict-free STS ----
    {
        int k  = lane & 15;
        int hb = (lane >> 4) << 4;
        bool valid = (k < KP);
        float kx=0.f, ky=0.f, kz=0.f;
        if (valid) { kx = s_kp[k*3+0]; ky = s_kp[k*3+1]; kz = s_kp[k*3+2]; }
        #pragma unroll 4
        for (int j = 0; j < 16; j++) {
            int h = hb + j;
            float val = 0.f;
            if (valid) {
                float dx = s_del[w][h][0] - kx;
                float dy = s_del[w][h][1] - ky;
                float dz = s_del[w][h][2] - kz;
                float sq = fmaf(dx,dx,fmaf(dy,dy,dz*dz));
                float dist = sqrtf(fmaxf(sq, 1e-12f));
                val = fmaxf(0.f, 1.f - dist*(1.f/KPEXT));
            }
            s_infl[w][h*16 + k] = val;
        }
    }
    __syncwarp();      // warp-local: phase 3 reads only this warp's point

    // ---- phase 3: acc over k-pairs with FFMA2 ----
    const int ch = lane*2;
    const float a1x = g_a1[ch], a1y = g_a1[ch+1];
    const float c1x = g_c1[ch], c1y = g_c1[ch+1];

    ull acc0[8], acc1[8];     // channel ch / ch+1; pair m = (k=2m, k=2m+1)
    #pragma unroll
    for (int m=0;m<8;m++) { acc0[m]=0ull; acc1[m]=0ull; }

    const float* inflp = s_infl[w];
    #pragma unroll 2
    for (int h = 0; h < HN; h++) {
        int idx = s_idx[w][h];
        float2 v = *(const float2*)&g_y1[(size_t)idx*MIDF + ch];
        v.x = fmaf(a1x, v.x, c1x); v.x = fmaxf(v.x, SLOPE*v.x);
        v.y = fmaf(a1y, v.y, c1y); v.y = fmaxf(v.y, SLOPE*v.y);
        ull vx2 = pack2(v.x, v.x);
        ull vy2 = pack2(v.y, v.y);

        const ulonglong2* fp = (const ulonglong2*)&inflp[h*16];
        ulonglong2 fA = fp[0], fB = fp[1], fC = fp[2], fD = fp[3];
        ull fk2[8] = {fA.x,fA.y,fB.x,fB.y,fC.x,fC.y,fD.x,fD.y};
        #pragma unroll
        for (int m=0;m<8;m++) {
            ffma2(acc0[m], vx2, fk2[m]);
            ffma2(acc1[m], vy2, fk2[m]);
        }
    }

    // ---- store: per k, warp writes 256B contiguous (float2 per lane) ----
    size_t base = (size_t)n*KPD + ch;
    #pragma unroll
    for (int m=0;m<8;m++) {
        float x0,x1,y0,y1;
        unpack2(acc0[m], x0, x1);   // ch   : k=2m, k=2m+1
        unpack2(acc1[m], y0, y1);   // ch+1 : k=2m, k=2m+1
        *(float2*)&g_wf[base + (size_t)(2*m)*MIDF] = make_float2(x0, y0);
        if (2*m+1 < KP)
            *(float2*)&g_wf[base + (size_t)(2*m+1)*MIDF] = make_float2(x1, y1);
    }
}

// ---------------- final: out = lrelu( lrelu(bn3(y3)) + lrelu(bnS(ysc)) ) ----------------
__global__ void final_kernel(float* __restrict__ out) {
    int i = blockIdx.x*blockDim.x + threadIdx.x;     // float4 index
    const int total4 = NPTS*OUTF/4;
    if (i >= total4) return;
    int c0 = (i << 2) & (OUTF-1);
    float4 y = *(const float4*)&g_y3[(size_t)i*4];
    float4 s = *(const float4*)&g_ysc[(size_t)i*4];
    float4 o;
    {
        float vy[4] = {y.x,y.y,y.z,y.w};
        float vs[4] = {s.x,s.y,s.z,s.w};
        float vo[4];
        #pragma unroll
        for (int j=0;j<4;j++) {
            int c = c0 + j;
            float a = fmaf(g_a3[c], vy[j], g_c3[c]); a = fmaxf(a, SLOPE*a);
            float b = fmaf(g_aS[c], vs[j], g_cS[c]); b = fmaxf(b, SLOPE*b);
            float r = a + b;
            vo[j] = fmaxf(r, SLOPE*r);
        }
        o = make_float4(vo[0],vo[1],vo[2],vo[3]);
    }
    *(float4*)&out[(size_t)i*4] = o;
}

// ---------------- launcher ----------------
extern "C" void kernel_launch(void* const* d_in, const int* in_sizes, int n_in,
                              void* d_out, int out_size) {
    const float* q    = (const float*)d_in[0];
    const float* s    = (const float*)d_in[1];
    const int*   inds = (const int*)  d_in[2];
    const float* feat = (const float*)d_in[3];
    const float* kp   = (const float*)d_in[4];
    const float* w1   = (const float*)d_in[5];
    const float* g1   = (const float*)d_in[6];
    const float* b1   = (const float*)d_in[7];
    const float* kw   = (const float*)d_in[8];
    const float* g2   = (const float*)d_in[9];
    const float* b2   = (const float*)d_in[10];
    const float* w3   = (const float*)d_in[11];
    const float* g3   = (const float*)d_in[12];
    const float* b3   = (const float*)d_in[13];
    const float* ws   = (const float*)d_in[14];
    const float* gs   = (const float*)d_in[15];
    const float* bs   = (const float*)d_in[16];
    float* out = (float*)d_out;

    const int MT = (NPTS + 127) / 128;   // 391 row tiles

    zero_stats_kernel<<<1, 256>>>();

    // conv1: y1 = feat @ w1, stats1
    gemm_kernel<128,64,16,8,8,false><<<dim3(MT,1), 128>>>(feat, w1, NPTS, INF, MIDF, 0);
    finalize_kernel<<<1, MIDF>>>(g1, b1, 0);

    // KPConv gather -> wf
    kpconv_kernel<<<NPTS/PPB, 256>>>(q, s, inds, kp);

    // x2 = wf @ kw  (kw viewed as [960,64]), stats2
    gemm_kernel<128,64,16,8,8,false><<<dim3(MT,1), 128>>>(nullptr, kw, NPTS, KPD, MIDF, 1);
    finalize_kernel<<<1, MIDF>>>(g2, b2, 1);

    // conv3: y3 = lrelu(bn2(x2)) @ w3, stats3
    gemm_kernel<128,128,16,8,8,true ><<<dim3(MT,2), 256>>>(nullptr, w3, NPTS, MIDF, OUTF, 2);
    // shortcut: ysc = feat @ ws, statsS
    gemm_kernel<128,128,16,8,8,false><<<dim3(MT,2), 256>>>(feat, ws, NPTS, INF, OUTF, 3);

    finalize_kernel<<<1, OUTF>>>(g3, b3, 2);
    finalize_kernel<<<1, OUTF>>>(gs, bs, 3);

    final_kernel<<<(NPTS*OUTF/4 + 255)/256, 256>>>(out);
}

// round 7
// speedup vs baseline: 1.4957x; 1.2220x over previous
#include <cuda_runtime.h>
#include <cuda_bf16.h>
#include <cstdint>

// ---------------- problem constants ----------------
#define NPTS  50000
#define HN    32
#define INF   128
#define MIDF  64
#define OUTF  256
#define KP    15
#define KPD   (KP*MIDF)      // 960
#define KPEXT 0.48f
#define BNEPS 1e-6f
#define SLOPE 0.1f

typedef unsigned long long ull;

// ---------------- packed f32x2 helpers ----------------
__device__ __forceinline__ ull pack2(float x, float y) {
    ull r; asm("mov.b64 %0, {%1, %2};" : "=l"(r) : "f"(x), "f"(y)); return r;
}
__device__ __forceinline__ void unpack2(ull v, float& x, float& y) {
    asm("mov.b64 {%0, %1}, %2;" : "=f"(x), "=f"(y) : "l"(v));
}
__device__ __forceinline__ void ffma2(ull& d, ull a, ull b) {
    asm("fma.rn.f32x2 %0, %1, %2, %0;" : "+l"(d) : "l"(a), "l"(b));
}

__device__ __forceinline__ uint32_t smem_u32(const void* p) {
    uint32_t a;
    asm("{ .reg .u64 t; cvta.to.shared.u64 t, %1; cvt.u32.u64 %0, t; }" : "=r"(a) : "l"(p));
    return a;
}

#define LDSM4(R, ADDR) \
    asm volatile("ldmatrix.sync.aligned.m8n8.x4.shared.b16 {%0,%1,%2,%3}, [%4];" \
        : "=r"((R)[0]), "=r"((R)[1]), "=r"((R)[2]), "=r"((R)[3]) : "r"(ADDR))

#define MMA16816(C, A, B0, B1) \
    asm volatile("mma.sync.aligned.m16n8k16.row.col.f32.bf16.bf16.f32 " \
        "{%0,%1,%2,%3}, {%4,%5,%6,%7}, {%8,%9}, {%0,%1,%2,%3};" \
        : "+f"((C)[0]), "+f"((C)[1]), "+f"((C)[2]), "+f"((C)[3]) \
        : "r"((A)[0]), "r"((A)[1]), "r"((A)[2]), "r"((A)[3]), "r"(B0), "r"(B1))

// ---------------- scratch ----------------
__device__ __align__(16) float g_y1 [NPTS*MIDF];
__device__ __align__(16) float g_x2 [NPTS*MIDF];
__device__ __align__(16) float g_y3 [NPTS*OUTF];
__device__ __align__(16) float g_ysc[NPTS*OUTF];

__device__ __align__(16) __nv_bfloat16 g_feat_hi[NPTS*INF], g_feat_lo[NPTS*INF];
__device__ __align__(16) __nv_bfloat16 g_wf_hi [NPTS*KPD], g_wf_lo [NPTS*KPD];
__device__ __align__(16) __nv_bfloat16 g_x2t_hi[NPTS*MIDF], g_x2t_lo[NPTS*MIDF];
__device__ __align__(16) __nv_bfloat16 g_w1t_hi[MIDF*INF],  g_w1t_lo[MIDF*INF];
__device__ __align__(16) __nv_bfloat16 g_kwt_hi[MIDF*KPD],  g_kwt_lo[MIDF*KPD];
__device__ __align__(16) __nv_bfloat16 g_w3t_hi[OUTF*MIDF], g_w3t_lo[OUTF*MIDF];
__device__ __align__(16) __nv_bfloat16 g_wst_hi[OUTF*INF],  g_wst_lo[OUTF*INF];

__device__ __align__(16) float g_sum1[MIDF], g_sq1[MIDF], g_a1[MIDF], g_c1[MIDF];
__device__ __align__(16) float g_sum2[MIDF], g_sq2[MIDF], g_a2[MIDF], g_c2[MIDF];
__device__ __align__(16) float g_sum3[OUTF], g_sq3[OUTF], g_a3[OUTF], g_c3[OUTF];
__device__ __align__(16) float g_sumS[OUTF], g_sqS[OUTF], g_aS[OUTF], g_cS[OUTF];

// ---------------- small kernels ----------------
__global__ void zero_stats_kernel() {
    int t = threadIdx.x;
    if (t < MIDF) { g_sum1[t]=0.f; g_sq1[t]=0.f; g_sum2[t]=0.f; g_sq2[t]=0.f; }
    g_sum3[t]=0.f; g_sq3[t]=0.f; g_sumS[t]=0.f; g_sqS[t]=0.f;
}

__global__ void finalize_kernel(const float* __restrict__ gg,
                                const float* __restrict__ bb, int which) {
    int t = threadIdx.x;
    const float* sum; const float* sq; float* a; float* c;
    switch (which) {
        case 0:  sum=g_sum1; sq=g_sq1; a=g_a1; c=g_c1; break;
        case 1:  sum=g_sum2; sq=g_sq2; a=g_a2; c=g_c2; break;
        case 2:  sum=g_sum3; sq=g_sq3; a=g_a3; c=g_c3; break;
        default: sum=g_sumS; sq=g_sqS; a=g_aS; c=g_cS; break;
    }
    const float inv = 1.0f / (float)NPTS;
    float m = sum[t] * inv;
    float v = sq[t] * inv - m * m;
    float av = gg[t] * rsqrtf(v + BNEPS);
    a[t] = av;
    c[t] = fmaf(-m, av, bb[t]);
}

__global__ void split_feat_kernel(const float* __restrict__ src) {
    int i = blockIdx.x*blockDim.x + threadIdx.x;
    if (i >= NPTS*INF) return;
    float x = src[i];
    __nv_bfloat16 h = __float2bfloat16(x);
    g_feat_hi[i] = h;
    g_feat_lo[i] = __float2bfloat16(x - __bfloat162float(h));
}

// transpose+split: src[K][N] -> dst[N][K]
__global__ void splitT_kernel(const float* __restrict__ src,
                              __nv_bfloat16* __restrict__ dh,
                              __nv_bfloat16* __restrict__ dl, int K, int N) {
    int i = blockIdx.x*blockDim.x + threadIdx.x;
    if (i >= K*N) return;
    int n = i / K;
    int k = i - n*K;
    float x = src[(size_t)k*N + n];
    __nv_bfloat16 h = __float2bfloat16(x);
    dh[i] = h;
    dl[i] = __float2bfloat16(x - __bfloat162float(h));
}

__global__ void split_x2t_kernel() {
    int i = blockIdx.x*blockDim.x + threadIdx.x;
    if (i >= NPTS*MIDF) return;
    int c = i & (MIDF-1);
    float x = g_x2[i];
    float v = fmaf(g_a2[c], x, g_c2[c]);
    v = fmaxf(v, SLOPE*v);
    __nv_bfloat16 h = __float2bfloat16(v);
    g_x2t_hi[i] = h;
    g_x2t_lo[i] = __float2bfloat16(v - __bfloat162float(h));
}

// ---------------- mma.sync bf16 GEMM: C[M,Ncol] = A[M,K] @ Bt[Ncol,K]^T ----
// Hi/lo split, 3 MMA passes per k16. Block: 256 thr = 8 warps (4m x 2n),
// tile 128x64, K-chunk 32, smem row stride 40 bf16 (conflict-free ldmatrix).
#define KC   32
#define KCP  40
__global__ void __launch_bounds__(256) mma_gemm_kernel(
        const __nv_bfloat16* __restrict__ Ahi,
        const __nv_bfloat16* __restrict__ Alo,
        const __nv_bfloat16* __restrict__ Bhi,
        const __nv_bfloat16* __restrict__ Blo,
        float* __restrict__ C,
        float* __restrict__ cS, float* __restrict__ cQ,
        int Ktot, int Ncol) {
    __shared__ __align__(16) __nv_bfloat16 sAh[128][KCP];
    __shared__ __align__(16) __nv_bfloat16 sAl[128][KCP];
    __shared__ __align__(16) __nv_bfloat16 sBh[64][KCP];
    __shared__ __align__(16) __nv_bfloat16 sBl[64][KCP];

    const int tid  = threadIdx.x;
    const int wid  = tid >> 5;
    const int lane = tid & 31;
    const int wr   = wid & 3;          // m-warp: rows wr*32..+31
    const int wc   = wid >> 2;         // n-warp: cols wc*32..+31
    const int row0 = blockIdx.x * 128;
    const int col0 = blockIdx.y * 64;

    float c[2][4][4];
    #pragma unroll
    for (int mb=0; mb<2; mb++)
        #pragma unroll
        for (int nb=0; nb<4; nb++)
            #pragma unroll
            for (int e=0; e<4; e++) c[mb][nb][e] = 0.f;

    const int nck = Ktot / KC;
    for (int ck = 0; ck < nck; ck++) {
        // ---- load A chunk: 128 rows x 32 bf16 (hi+lo) ----
        {
            int r    = tid >> 1;
            int half = tid & 1;
            int grow = row0 + r;
            const uint4* sh = (const uint4*)(Ahi + (size_t)grow*Ktot + ck*KC) + half*2;
            const uint4* sl = (const uint4*)(Alo + (size_t)grow*Ktot + ck*KC) + half*2;
            bool v = grow < NPTS;
            #pragma unroll
            for (int j=0;j<2;j++) {
                uint4 vh = v ? sh[j] : make_uint4(0,0,0,0);
                uint4 vl = v ? sl[j] : make_uint4(0,0,0,0);
                *(uint4*)&sAh[r][half*16 + j*8] = vh;
                *(uint4*)&sAl[r][half*16 + j*8] = vl;
            }
        }
        // ---- load B chunk: 64 rows x 32 bf16 (hi+lo) ----
        {
            int r = tid >> 2;
            int j = tid & 3;
            const uint4* sh = (const uint4*)(Bhi + (size_t)(col0 + r)*Ktot + ck*KC);
            const uint4* sl = (const uint4*)(Blo + (size_t)(col0 + r)*Ktot + ck*KC);
            *(uint4*)&sBh[r][j*8] = sh[j];
            *(uint4*)&sBl[r][j*8] = sl[j];
        }
        __syncthreads();

        #pragma unroll
        for (int s = 0; s < 2; s++) {
            const int k0 = s*16;
            const int lrow = lane & 15;
            const int lcol = k0 + ((lane >> 4) << 3);
            uint32_t a_h[2][4], a_l[2][4], b_h[2][4], b_l[2][4];
            #pragma unroll
            for (int mb=0; mb<2; mb++) {
                int r = wr*32 + mb*16 + lrow;
                LDSM4(a_h[mb], smem_u32(&sAh[r][lcol]));
                LDSM4(a_l[mb], smem_u32(&sAl[r][lcol]));
            }
            #pragma unroll
            for (int g=0; g<2; g++) {
                int r = wc*32 + g*16 + lrow;
                LDSM4(b_h[g], smem_u32(&sBh[r][lcol]));
                LDSM4(b_l[g], smem_u32(&sBl[r][lcol]));
            }
            #pragma unroll
            for (int mb=0; mb<2; mb++) {
                #pragma unroll
                for (int nb=0; nb<4; nb++) {
                    int g = nb >> 1, h = nb & 1;
                    MMA16816(c[mb][nb], a_h[mb], b_h[g][h], b_h[g][h+2]);
                    MMA16816(c[mb][nb], a_h[mb], b_l[g][h], b_l[g][h+2]);
                    MMA16816(c[mb][nb], a_l[mb], b_h[g][h], b_h[g][h+2]);
                }
            }
        }
        __syncthreads();
    }

    // ---- epilogue: store + per-column (sum, sumsq) ----
    #pragma unroll
    for (int nb=0; nb<4; nb++) {
        int ncol = col0 + wc*32 + nb*8 + (lane & 3)*2;
        float s0=0.f,q0=0.f,s1=0.f,q1=0.f;
        #pragma unroll
        for (int mb=0; mb<2; mb++) {
            int m0 = row0 + wr*32 + mb*16 + (lane >> 2);
            bool vA = m0 < NPTS, vB = (m0+8) < NPTS;
            float v0 = c[mb][nb][0], v1 = c[mb][nb][1];
            float v2 = c[mb][nb][2], v3 = c[mb][nb][3];
            if (vA) {
                *(float2*)&C[(size_t)m0*Ncol + ncol] = make_float2(v0, v1);
                s0 += v0; q0 += v0*v0; s1 += v1; q1 += v1*v1;
            }
            if (vB) {
                *(float2*)&C[(size_t)(m0+8)*Ncol + ncol] = make_float2(v2, v3);
                s0 += v2; q0 += v2*v2; s1 += v3; q1 += v3*v3;
            }
        }
        #pragma unroll
        for (int o=16;o>=4;o>>=1) {
            s0 += __shfl_xor_sync(0xffffffffu, s0, o);
            q0 += __shfl_xor_sync(0xffffffffu, q0, o);
            s1 += __shfl_xor_sync(0xffffffffu, s1, o);
            q1 += __shfl_xor_sync(0xffffffffu, q1, o);
        }
        if ((lane >> 2) == 0) {
            atomicAdd(&cS[ncol],   s0);
            atomicAdd(&cQ[ncol],   q0);
            atomicAdd(&cS[ncol+1], s1);
            atomicAdd(&cQ[ncol+1], q1);
        }
    }
}

// ---------------- KPConv gather: warp == point, 2 channels/thread,
//                  writes wf as bf16 hi/lo split ----------------
#define PPB 8
__global__ void __launch_bounds__(256) kpconv_kernel(
                              const float* __restrict__ qpts,
                              const float* __restrict__ spts,
                              const int*   __restrict__ inds,
                              const float* __restrict__ kpts) {
    __shared__ __align__(16) float s_infl[PPB][HN*16];
    __shared__ __align__(16) float s_del[PPB][HN][3];
    __shared__ int   s_idx[PPB][HN];
    __shared__ float s_kp[KP*3];

    const int tid  = threadIdx.x;
    const int w    = tid >> 5;
    const int lane = tid & 31;
    const int n = blockIdx.x * PPB + w;

    if (tid < KP*3) s_kp[tid] = kpts[tid];

    {
        int idx = inds[n*HN + lane];
        s_idx[w][lane] = idx;
        s_del[w][lane][0] = spts[idx*3+0] - qpts[n*3+0];
        s_del[w][lane][1] = spts[idx*3+1] - qpts[n*3+1];
        s_del[w][lane][2] = spts[idx*3+2] - qpts[n*3+2];
    }
    __syncthreads();

    {
        int k  = lane & 15;
        int hb = (lane >> 4) << 4;
        bool valid = (k < KP);
        float kx=0.f, ky=0.f, kz=0.f;
        if (valid) { kx = s_kp[k*3+0]; ky = s_kp[k*3+1]; kz = s_kp[k*3+2]; }
        #pragma unroll 4
        for (int j = 0; j < 16; j++) {
            int h = hb + j;
            float val = 0.f;
            if (valid) {
                float dx = s_del[w][h][0] - kx;
                float dy = s_del[w][h][1] - ky;
                float dz = s_del[w][h][2] - kz;
                float sq = fmaf(dx,dx,fmaf(dy,dy,dz*dz));
                float dist = sqrtf(fmaxf(sq, 1e-12f));
                val = fmaxf(0.f, 1.f - dist*(1.f/KPEXT));
            }
            s_infl[w][h*16 + k] = val;
        }
    }
    __syncwarp();

    const int ch = lane*2;
    const float a1x = g_a1[ch], a1y = g_a1[ch+1];
    const float c1x = g_c1[ch], c1y = g_c1[ch+1];

    ull acc0[8], acc1[8];
    #pragma unroll
    for (int m=0;m<8;m++) { acc0[m]=0ull; acc1[m]=0ull; }

    const float* inflp = s_infl[w];
    #pragma unroll 2
    for (int h = 0; h < HN; h++) {
        int idx = s_idx[w][h];
        float2 v = *(const float2*)&g_y1[(size_t)idx*MIDF + ch];
        v.x = fmaf(a1x, v.x, c1x); v.x = fmaxf(v.x, SLOPE*v.x);
        v.y = fmaf(a1y, v.y, c1y); v.y = fmaxf(v.y, SLOPE*v.y);
        ull vx2 = pack2(v.x, v.x);
        ull vy2 = pack2(v.y, v.y);

        const ulonglong2* fp = (const ulonglong2*)&inflp[h*16];
        ulonglong2 fA = fp[0], fB = fp[1], fC = fp[2], fD = fp[3];
        ull fk2[8] = {fA.x,fA.y,fB.x,fB.y,fC.x,fC.y,fD.x,fD.y};
        #pragma unroll
        for (int m=0;m<8;m++) {
            ffma2(acc0[m], vx2, fk2[m]);
            ffma2(acc1[m], vy2, fk2[m]);
        }
    }

    size_t base = (size_t)n*KPD + ch;
    #pragma unroll
    for (int m=0;m<8;m++) {
        float x0,x1,y0,y1;
        unpack2(acc0[m], x0, x1);
        unpack2(acc1[m], y0, y1);
        {
            __nv_bfloat16 hx = __float2bfloat16(x0), hy = __float2bfloat16(y0);
            __nv_bfloat162 hv; hv.x = hx; hv.y = hy;
            __nv_bfloat162 lv;
            lv.x = __float2bfloat16(x0 - __bfloat162float(hx));
            lv.y = __float2bfloat16(y0 - __bfloat162float(hy));
            *(__nv_bfloat162*)&g_wf_hi[base + (size_t)(2*m)*MIDF] = hv;
            *(__nv_bfloat162*)&g_wf_lo[base + (size_t)(2*m)*MIDF] = lv;
        }
        if (2*m+1 < KP) {
            __nv_bfloat16 hx = __float2bfloat16(x1), hy = __float2bfloat16(y1);
            __nv_bfloat162 hv; hv.x = hx; hv.y = hy;
            __nv_bfloat162 lv;
            lv.x = __float2bfloat16(x1 - __bfloat162float(hx));
            lv.y = __float2bfloat16(y1 - __bfloat162float(hy));
            *(__nv_bfloat162*)&g_wf_hi[base + (size_t)(2*m+1)*MIDF] = hv;
            *(__nv_bfloat162*)&g_wf_lo[base + (size_t)(2*m+1)*MIDF] = lv;
        }
    }
}

// ---------------- final ----------------
__global__ void final_kernel(float* __restrict__ out) {
    int i = blockIdx.x*blockDim.x + threadIdx.x;
    const int total4 = NPTS*OUTF/4;
    if (i >= total4) return;
    int c0 = (i << 2) & (OUTF-1);
    float4 y = *(const float4*)&g_y3[(size_t)i*4];
    float4 s = *(const float4*)&g_ysc[(size_t)i*4];
    float vy[4] = {y.x,y.y,y.z,y.w};
    float vs[4] = {s.x,s.y,s.z,s.w};
    float vo[4];
    #pragma unroll
    for (int j=0;j<4;j++) {
        int c = c0 + j;
        float a = fmaf(g_a3[c], vy[j], g_c3[c]); a = fmaxf(a, SLOPE*a);
        float b = fmaf(g_aS[c], vs[j], g_cS[c]); b = fmaxf(b, SLOPE*b);
        float r = a + b;
        vo[j] = fmaxf(r, SLOPE*r);
    }
    *(float4*)&out[(size_t)i*4] = make_float4(vo[0],vo[1],vo[2],vo[3]);
}

// ---------------- launcher ----------------
extern "C" void kernel_launch(void* const* d_in, const int* in_sizes, int n_in,
                              void* d_out, int out_size) {
    const float* q    = (const float*)d_in[0];
    const float* s    = (const float*)d_in[1];
    const int*   inds = (const int*)  d_in[2];
    const float* feat = (const float*)d_in[3];
    const float* kp   = (const float*)d_in[4];
    const float* w1   = (const float*)d_in[5];
    const float* g1   = (const float*)d_in[6];
    const float* b1   = (const float*)d_in[7];
    const float* kw   = (const float*)d_in[8];
    const float* g2   = (const float*)d_in[9];
    const float* b2   = (const float*)d_in[10];
    const float* w3   = (const float*)d_in[11];
    const float* g3   = (const float*)d_in[12];
    const float* b3   = (const float*)d_in[13];
    const float* ws   = (const float*)d_in[14];
    const float* gs   = (const float*)d_in[15];
    const float* bs   = (const float*)d_in[16];
    float* out = (float*)d_out;

    float *p_y1, *p_x2, *p_y3, *p_ysc;
    float *p_sum1,*p_sq1,*p_sum2,*p_sq2,*p_sum3,*p_sq3,*p_sumS,*p_sqS;
    __nv_bfloat16 *p_fh,*p_fl,*p_wfh,*p_wfl,*p_x2h,*p_x2l;
    __nv_bfloat16 *p_w1h,*p_w1l,*p_kwh,*p_kwl,*p_w3h,*p_w3l,*p_wsh,*p_wsl;
    cudaGetSymbolAddress((void**)&p_y1,  g_y1);
    cudaGetSymbolAddress((void**)&p_x2,  g_x2);
    cudaGetSymbolAddress((void**)&p_y3,  g_y3);
    cudaGetSymbolAddress((void**)&p_ysc, g_ysc);
    cudaGetSymbolAddress((void**)&p_sum1, g_sum1); cudaGetSymbolAddress((void**)&p_sq1, g_sq1);
    cudaGetSymbolAddress((void**)&p_sum2, g_sum2); cudaGetSymbolAddress((void**)&p_sq2, g_sq2);
    cudaGetSymbolAddress((void**)&p_sum3, g_sum3); cudaGetSymbolAddress((void**)&p_sq3, g_sq3);
    cudaGetSymbolAddress((void**)&p_sumS, g_sumS); cudaGetSymbolAddress((void**)&p_sqS, g_sqS);
    cudaGetSymbolAddress((void**)&p_fh,  g_feat_hi); cudaGetSymbolAddress((void**)&p_fl,  g_feat_lo);
    cudaGetSymbolAddress((void**)&p_wfh, g_wf_hi);   cudaGetSymbolAddress((void**)&p_wfl, g_wf_lo);
    cudaGetSymbolAddress((void**)&p_x2h, g_x2t_hi);  cudaGetSymbolAddress((void**)&p_x2l, g_x2t_lo);
    cudaGetSymbolAddress((void**)&p_w1h, g_w1t_hi);  cudaGetSymbolAddress((void**)&p_w1l, g_w1t_lo);
    cudaGetSymbolAddress((void**)&p_kwh, g_kwt_hi);  cudaGetSymbolAddress((void**)&p_kwl, g_kwt_lo);
    cudaGetSymbolAddress((void**)&p_w3h, g_w3t_hi);  cudaGetSymbolAddress((void**)&p_w3l, g_w3t_lo);
    cudaGetSymbolAddress((void**)&p_wsh, g_wst_hi);  cudaGetSymbolAddress((void**)&p_wsl, g_wst_lo);

    const int MT = (NPTS + 127) / 128;   // 391 row tiles

    zero_stats_kernel<<<1, 256>>>();

    // prep: splits + weight transposes
    split_feat_kernel<<<(NPTS*INF + 255)/256, 256>>>(feat);
    splitT_kernel<<<(INF*MIDF  + 255)/256, 256>>>(w1, p_w1h, p_w1l, INF,  MIDF);
    splitT_kernel<<<(KPD*MIDF  + 255)/256, 256>>>(kw, p_kwh, p_kwl, KPD,  MIDF);
    splitT_kernel<<<(MIDF*OUTF + 255)/256, 256>>>(w3, p_w3h, p_w3l, MIDF, OUTF);
    splitT_kernel<<<(INF*OUTF  + 255)/256, 256>>>(ws, p_wsh, p_wsl, INF,  OUTF);

    // conv1: y1 = feat @ w1
    mma_gemm_kernel<<<dim3(MT,1), 256>>>(p_fh, p_fl, p_w1h, p_w1l, p_y1, p_sum1, p_sq1, INF, MIDF);
    finalize_kernel<<<1, MIDF>>>(g1, b1, 0);

    // KPConv gather -> wf (bf16 hi/lo)
    kpconv_kernel<<<NPTS/PPB, 256>>>(q, s, inds, kp);

    // conv2: x2 = wf @ kw
    mma_gemm_kernel<<<dim3(MT,1), 256>>>(p_wfh, p_wfl, p_kwh, p_kwl, p_x2, p_sum2, p_sq2, KPD, MIDF);
    finalize_kernel<<<1, MIDF>>>(g2, b2, 1);

    // bn2+lrelu+split
    split_x2t_kernel<<<(NPTS*MIDF + 255)/256, 256>>>();

    // conv3: y3 = x2t @ w3
    mma_gemm_kernel<<<dim3(MT,4), 256>>>(p_x2h, p_x2l, p_w3h, p_w3l, p_y3, p_sum3, p_sq3, MIDF, OUTF);
    // shortcut: ysc = feat @ ws
    mma_gemm_kernel<<<dim3(MT,4), 256>>>(p_fh, p_fl, p_wsh, p_wsl, p_ysc, p_sumS, p_sqS, INF, OUTF);

    finalize_kernel<<<1, OUTF>>>(g3, b3, 2);
    finalize_kernel<<<1, OUTF>>>(gs, bs, 3);

    final_kernel<<<(NPTS*OUTF/4 + 255)/256, 256>>>(out);
}